// round 16
// baseline (speedup 1.0000x reference)
#include <cuda_runtime.h>
#include <cuda_bf16.h>
#include <cstdint>
#include <math.h>

#define EPSV 1e-5f
constexpr int B     = 8;
constexpr int C     = 512;
constexpr int NH    = 8;
constexpr int KD    = 32;
constexpr int HD    = 64;
constexpr int HQKV  = 1024;
constexpr int NPIX  = 1600;
constexpr int IH    = 40;
constexpr int IW    = 40;
constexpr int K3    = 1536;
constexpr int PGRID = 304;            // 2 CTAs x 152 SMs
constexpr float SCALE = 0.17677669529663687f;

__device__ __align__(16) __nv_bfloat16 g_wcq[(size_t)HQKV * K3];
__device__ __align__(16) __nv_bfloat16 g_wcp[(size_t)C * K3];
__device__ __align__(16) __nv_bfloat16 g_xc [(size_t)B * NPIX * K3];
__device__ __align__(16) __nv_bfloat16 g_qt[(size_t)64 * 1664 * 96];
__device__ __align__(16) __nv_bfloat16 g_kt[(size_t)64 * 1600 * 96];
__device__ __align__(16) __nv_bfloat16 g_vh[(size_t)64 * 64 * 1600];
__device__ __align__(16) __nv_bfloat16 g_vl[(size_t)64 * 64 * 1600];

// ===================== helpers =====================
__device__ __forceinline__ float bf_round(float x) {
    return __bfloat162float(__float2bfloat16_rn(x));
}
__device__ __forceinline__ uint32_t pack2(float hi, float lo) {
    uint32_t r;
    asm("cvt.rn.bf16x2.f32 %0, %1, %2;" : "=r"(r) : "f"(hi), "f"(lo));
    return r;
}
__device__ __forceinline__ void mma16816(float* c, const uint32_t* a, uint32_t b0, uint32_t b1) {
    asm volatile(
        "mma.sync.aligned.m16n8k16.row.col.f32.bf16.bf16.f32 "
        "{%0,%1,%2,%3}, {%4,%5,%6,%7}, {%8,%9}, {%0,%1,%2,%3};"
        : "+f"(c[0]), "+f"(c[1]), "+f"(c[2]), "+f"(c[3])
        : "r"(a[0]), "r"(a[1]), "r"(a[2]), "r"(a[3]), "r"(b0), "r"(b1));
}
__device__ __forceinline__ void ldsm4(uint32_t* r, uint32_t a) {
    asm volatile("ldmatrix.sync.aligned.m8n8.x4.shared.b16 {%0,%1,%2,%3}, [%4];"
        : "=r"(r[0]), "=r"(r[1]), "=r"(r[2]), "=r"(r[3]) : "r"(a));
}
__device__ __forceinline__ void cp16(uint32_t dst, const void* src) {
    asm volatile("cp.async.cg.shared.global [%0], [%1], 16;" :: "r"(dst), "l"(src));
}
#define CP_COMMIT() asm volatile("cp.async.commit_group;" ::: "memory")
#define CP_WAIT(n)  asm volatile("cp.async.wait_group %0;" :: "n"(n) : "memory")

// ================= prep: W -> triple bf16 [m][3k]: (h,h,l) ==================
__global__ __launch_bounds__(256) void prep_w(const float* __restrict__ W,
                                              __nv_bfloat16* __restrict__ out, int MK)
{
    int i = blockIdx.x * 256 + threadIdx.x;
    if (i >= MK) return;
    int m = i >> 9, k = i & 511;
    float v = W[i];
    float h = bf_round(v);
    __nv_bfloat16* d = out + (size_t)m * K3 + 3 * k;
    d[0] = __float2bfloat16_rn(h);
    d[1] = __float2bfloat16_rn(h);
    d[2] = __float2bfloat16_rn(v - h);
}

// ====== prep: X [b][k][n] -> triple bf16 [b][n][3k]: (h,l,h), vectorized ====
__global__ __launch_bounds__(256) void prep_xt(const float* __restrict__ X,
                                               __nv_bfloat16* __restrict__ out)
{
    __shared__ __align__(16) __nv_bfloat16 s[64 * 112];
    const int tid = threadIdx.x;
    const int k0 = blockIdx.x * 32, n0 = blockIdx.y * 64, b = blockIdx.z;
    const float* Xb = X + (size_t)b * 512 * NPIX;

    #pragma unroll
    for (int i = 0; i < 8; i++) {
        int idx = tid + i * 256;
        int k = idx >> 6, n = idx & 63;
        float v = Xb[(size_t)(k0 + k) * NPIX + n0 + n];
        float h = bf_round(v);
        __nv_bfloat16 hb = __float2bfloat16_rn(h);
        s[n * 112 + 3 * k]     = hb;
        s[n * 112 + 3 * k + 1] = __float2bfloat16_rn(v - h);
        s[n * 112 + 3 * k + 2] = hb;
    }
    __syncthreads();

    __nv_bfloat16* dst = out + (size_t)b * NPIX * K3 + (size_t)n0 * K3 + k0 * 3;
    #pragma unroll
    for (int i = 0; i < 3; i++) {
        int c = tid + i * 256;
        int row = c / 12, col = c % 12;
        float4 val = *(const float4*)&s[row * 112 + col * 8];
        *(float4*)(dst + (size_t)row * K3 + col * 8) = val;
    }
}

// ====== persistent 3-stage bf16 GEMM (K'=1536, KC=64) + fused BN ============
constexpr int KC    = 64;
constexpr int NIT   = K3 / KC;                 // 24
constexpr int OPB   = 128 * 144;
constexpr int STAGE = 2 * OPB;                 // 36864
constexpr int GSMEM = 3 * STAGE;               // 110592

__global__ __launch_bounds__(256, 2) void gemm3_bn(
    const __nv_bfloat16* __restrict__ wc, const __nv_bfloat16* __restrict__ xc,
    const float* __restrict__ gamma, const float* __restrict__ beta,
    const float* __restrict__ mean,  const float* __restrict__ var,
    float* __restrict__ out, int M, int fuse, int NT)
{
    extern __shared__ __align__(16) char dsm[];
    __shared__ float sbn[128][2];

    const int tid  = threadIdx.x;
    const int wid  = tid >> 5;
    const int lane = tid & 31;
    const int g    = lane >> 2;
    const int tig  = lane & 3;
    const int wm   = wid >> 1;
    const int wn   = wid & 1;
    const int MT   = M >> 7;                   // m-tiles

    const uint32_t sb = (uint32_t)__cvta_generic_to_shared(dsm);
    const int rowA = wm * 32 + (lane & 15);
    const uint32_t colA = (lane & 16) ? 16u : 0u;
    const int rowB = (lane & 7) + ((lane & 16) >> 1);
    const uint32_t colB = (lane & 8) ? 16u : 0u;

    int rowL[4], segL[4];
    #pragma unroll
    for (int j = 0; j < 4; j++) {
        int id = tid + j * 256;
        rowL[j] = id >> 3; segL[j] = id & 7;
    }

    for (int tile = blockIdx.x; tile < NT; tile += PGRID) {
        const int n0 = (tile % 13) * 128;
        int rest = tile / 13;
        const int m0 = (rest % MT) * 128;
        const int b  = rest / MT;
        const __nv_bfloat16* xb = xc + (size_t)b * NPIX * K3;

        CP_WAIT(0);
        __syncthreads();                       // smem free for reuse

        if (tid < 128) {
            int m = m0 + tid;
            float inv = gamma[m] * rsqrtf(var[m] + EPSV);
            sbn[tid][0] = inv;
            sbn[tid][1] = beta[m] - mean[m] * inv;
        }

        int nCl[4];
        #pragma unroll
        for (int j = 0; j < 4; j++) {
            int n = n0 + rowL[j]; if (n > NPIX - 1) n = NPIX - 1;
            nCl[j] = n;
        }

        float acc[2][8][4];
        #pragma unroll
        for (int i = 0; i < 2; i++)
            #pragma unroll
            for (int j = 0; j < 8; j++)
                #pragma unroll
                for (int l = 0; l < 4; l++) acc[i][j][l] = 0.f;

        auto issue = [&](int buf, int k0) {
            uint32_t bo = sb + buf * STAGE;
            #pragma unroll
            for (int j = 0; j < 4; j++) {
                uint32_t d = rowL[j] * 144 + segL[j] * 16;
                cp16(bo + d,       wc + (size_t)(m0 + rowL[j]) * K3 + k0 + segL[j] * 8);
                cp16(bo + OPB + d, xb + (size_t)nCl[j] * K3 + k0 + segL[j] * 8);
            }
        };

        issue(0, 0);  CP_COMMIT();
        issue(1, KC); CP_COMMIT();

        int rd = 0, wr = 2;
        #pragma unroll 1
        for (int it = 0; it < NIT; it++) {
            CP_WAIT(1);
            __syncthreads();
            if (it + 2 < NIT) issue(wr, (it + 2) * KC);
            CP_COMMIT();

            const uint32_t aBase = sb + rd * STAGE + rowA * 144 + colA;
            const uint32_t bBase = sb + rd * STAGE + OPB + (wn * 64 + rowB) * 144 + colB;
            #pragma unroll
            for (int ks = 0; ks < 4; ks++) {
                uint32_t aW[2][4];
                ldsm4(aW[0], aBase + ks * 32);
                ldsm4(aW[1], aBase + 2304 + ks * 32);
                #pragma unroll
                for (int np = 0; np < 4; np++) {
                    uint32_t bq[4];
                    ldsm4(bq, bBase + np * 2304 + ks * 32);
                    mma16816(acc[0][2 * np],     aW[0], bq[0], bq[1]);
                    mma16816(acc[1][2 * np],     aW[1], bq[0], bq[1]);
                    mma16816(acc[0][2 * np + 1], aW[0], bq[2], bq[3]);
                    mma16816(acc[1][2 * np + 1], aW[1], bq[2], bq[3]);
                }
            }
            rd = (rd == 2) ? 0 : rd + 1;
            wr = (wr == 2) ? 0 : wr + 1;
        }

        if (!fuse) {
            #pragma unroll
            for (int mf = 0; mf < 2; mf++) {
                int mla = wm * 32 + mf * 16 + g;
                int mlb = mla + 8;
                float inva = sbn[mla][0], adda = sbn[mla][1];
                float invb = sbn[mlb][0], addb = sbn[mlb][1];
                float* rowa = out + ((size_t)b * M + m0 + mla) * NPIX;
                float* rowb = out + ((size_t)b * M + m0 + mlb) * NPIX;
                #pragma unroll
                for (int nf = 0; nf < 8; nf++) {
                    int n = n0 + wn * 64 + nf * 8 + 2 * tig;
                    if (n < NPIX) {
                        *(float2*)&rowa[n] = make_float2(acc[mf][nf][0] * inva + adda,
                                                         acc[mf][nf][1] * inva + adda);
                        *(float2*)&rowb[n] = make_float2(acc[mf][nf][2] * invb + addb,
                                                         acc[mf][nf][3] * invb + addb);
                    }
                }
            }
            continue;
        }

        // ---- fused qkv epilogue ----
        const int bh = b * NH + (m0 >> 7);
        __syncthreads();
        __nv_bfloat16* sq  = (__nv_bfloat16*)dsm;            // [128 n][104]
        __nv_bfloat16* sk2 = (__nv_bfloat16*)(dsm + 26624);  // [128 n][104]

        if (wm < 2) {
            __nv_bfloat16* sdst = (wm == 0) ? sq : sk2;
            const bool isQ = (wm == 0);
            #pragma unroll
            for (int mf = 0; mf < 2; mf++) {
                #pragma unroll
                for (int e = 0; e < 2; e++) {
                    int c  = mf * 16 + g + e * 8;
                    int ml = wm * 32 + c;
                    float inv = sbn[ml][0], add = sbn[ml][1];
                    #pragma unroll
                    for (int nf = 0; nf < 8; nf++) {
                        int nl = wn * 64 + nf * 8 + 2 * tig;
                        float v0 = acc[mf][nf][2 * e]     * inv + add;
                        float v1 = acc[mf][nf][2 * e + 1] * inv + add;
                        if (isQ) { v0 *= SCALE; v1 *= SCALE; }
                        float h0 = bf_round(v0), h1 = bf_round(v1);
                        __nv_bfloat16 hb0 = __float2bfloat16_rn(h0);
                        __nv_bfloat16 hb1 = __float2bfloat16_rn(h1);
                        __nv_bfloat16 lb0 = __float2bfloat16_rn(v0 - h0);
                        __nv_bfloat16 lb1 = __float2bfloat16_rn(v1 - h1);
                        if (isQ) {
                            sdst[nl * 104 + 3 * c]     = hb0;
                            sdst[nl * 104 + 3 * c + 1] = hb0;
                            sdst[nl * 104 + 3 * c + 2] = lb0;
                            sdst[(nl + 1) * 104 + 3 * c]     = hb1;
                            sdst[(nl + 1) * 104 + 3 * c + 1] = hb1;
                            sdst[(nl + 1) * 104 + 3 * c + 2] = lb1;
                        } else {
                            sdst[nl * 104 + 3 * c]     = hb0;
                            sdst[nl * 104 + 3 * c + 1] = lb0;
                            sdst[nl * 104 + 3 * c + 2] = hb0;
                            sdst[(nl + 1) * 104 + 3 * c]     = hb1;
                            sdst[(nl + 1) * 104 + 3 * c + 1] = lb1;
                            sdst[(nl + 1) * 104 + 3 * c + 2] = hb1;
                        }
                    }
                }
            }
        } else {
            #pragma unroll
            for (int mf = 0; mf < 2; mf++) {
                #pragma unroll
                for (int e = 0; e < 2; e++) {
                    int ml = wm * 32 + mf * 16 + g + e * 8;
                    int d  = ml - 64;
                    float inv = sbn[ml][0], add = sbn[ml][1];
                    __nv_bfloat16* vhrow = g_vh + ((size_t)bh * 64 + d) * 1600;
                    __nv_bfloat16* vlrow = g_vl + ((size_t)bh * 64 + d) * 1600;
                    #pragma unroll
                    for (int nf = 0; nf < 8; nf++) {
                        int n = n0 + wn * 64 + nf * 8 + 2 * tig;
                        if (n < NPIX) {
                            float v0 = acc[mf][nf][2 * e]     * inv + add;
                            float v1 = acc[mf][nf][2 * e + 1] * inv + add;
                            float h0 = bf_round(v0), h1 = bf_round(v1);
                            *(uint32_t*)(vhrow + n) = pack2(h1, h0);
                            *(uint32_t*)(vlrow + n) = pack2(v1 - h1, v0 - h0);
                        }
                    }
                }
            }
        }
        __syncthreads();

        __nv_bfloat16* qd = g_qt + ((size_t)bh * 1664 + n0) * 96;
        __nv_bfloat16* kd = g_kt + ((size_t)bh * 1600 + n0) * 96;
        #pragma unroll
        for (int i = 0; i < 6; i++) {
            int cch = tid + i * 256;
            int row = cch / 12, seg = cch % 12;
            *(float4*)(qd + (size_t)row * 96 + seg * 8) = *(const float4*)&sq[row * 104 + seg * 8];
            if (n0 + row < NPIX)
                *(float4*)(kd + (size_t)row * 96 + seg * 8) = *(const float4*)&sk2[row * 104 + seg * 8];
        }
    }
}

// ===== persistent attention + fused (dwconv-pe + add + y -> g_xc) ===========
constexpr int ASM_K0 = 26624;
constexpr int ASM_V0 = 53248;
constexpr int ASM_W  = 33792;
constexpr int ASMEM  = 90112;

__global__ __launch_bounds__(256, 2) void attn2_kernel(
    const float* __restrict__ pw,
    const float* __restrict__ pg, const float* __restrict__ pb,
    const float* __restrict__ pm, const float* __restrict__ pv)
{
    extern __shared__ __align__(16) char sm[];
    const uint32_t sb = (uint32_t)__cvta_generic_to_shared(sm);
    const __nv_bfloat16* sQ = (const __nv_bfloat16*)sm;
    float* sO = (float*)sm;

    const int tid  = threadIdx.x;
    const int wid  = tid >> 5;
    const int lane = tid & 31;
    const int g    = lane >> 2;
    const int tig  = lane & 3;

    const int rowB = (lane & 7) + ((lane & 16) >> 1);
    const uint32_t colB = (lane & 8) ? 16u : 0u;

    for (int unit = blockIdx.x; unit < 13 * 64; unit += PGRID) {
        const int q0 = (unit % 13) * 128;
        const int bh = unit / 13;

        const __nv_bfloat16* qt  = g_qt + (size_t)bh * 1664 * 96;
        const __nv_bfloat16* kt  = g_kt + (size_t)bh * 1600 * 96;
        const __nv_bfloat16* vhp = g_vh + (size_t)bh * 64 * 1600;
        const __nv_bfloat16* vlp = g_vl + (size_t)bh * 64 * 1600;

        CP_WAIT(0);
        __syncthreads();

        auto issueKV = [&](int buf, int t) {
            uint32_t kb = sb + ASM_K0 + buf * 13312;
            #pragma unroll
            for (int j = 0; j < 3; j++) {
                int id = tid + j * 256;
                int row = id / 12, seg = id % 12;
                cp16(kb + row * 208 + seg * 16, kt + ((size_t)(t * 64 + row)) * 96 + seg * 8);
            }
            uint32_t vb = sb + ASM_V0 + buf * 18432;
            #pragma unroll
            for (int j = 0; j < 4; j++) {
                int id = tid + j * 256;
                int half = id >> 9, r = id & 511;
                int row = r >> 3, seg = r & 7;
                const __nv_bfloat16* src = (half ? vlp : vhp) + (size_t)row * 1600 + t * 64 + seg * 8;
                cp16(vb + half * 9216 + row * 144 + seg * 16, src);
            }
        };

        #pragma unroll
        for (int j = 0; j < 6; j++) {
            int id = tid + j * 256;
            int row = id / 12, seg = id % 12;
            cp16(sb + row * 208 + seg * 16, qt + (size_t)(q0 + row) * 96 + seg * 8);
        }
        issueKV(0, 0);
        CP_COMMIT();

        uint32_t aQ[6][4];
        float o[8][4];
        #pragma unroll
        for (int i = 0; i < 8; i++)
            #pragma unroll
            for (int j = 0; j < 4; j++) o[i][j] = 0.f;
        float rsum0 = 0.f, rsum1 = 0.f;

        int buf = 0;
        #pragma unroll 1
        for (int t = 0; t < 25; t++) {
            if (t + 1 < 25) { issueKV(buf ^ 1, t + 1); CP_COMMIT(); CP_WAIT(1); }
            else            { CP_WAIT(0); }
            __syncthreads();

            if (t == 0) {
                int r0 = wid * 16 + g;
                #pragma unroll
                for (int ks = 0; ks < 6; ks++) {
                    int cb = ks * 16 + 2 * tig;
                    aQ[ks][0] = *(const uint32_t*)&sQ[r0 * 104 + cb];
                    aQ[ks][1] = *(const uint32_t*)&sQ[(r0 + 8) * 104 + cb];
                    aQ[ks][2] = *(const uint32_t*)&sQ[r0 * 104 + cb + 8];
                    aQ[ks][3] = *(const uint32_t*)&sQ[(r0 + 8) * 104 + cb + 8];
                }
            }

            const uint32_t kBase = sb + ASM_K0 + buf * 13312 + rowB * 208 + colB;
            const uint32_t vBase = sb + ASM_V0 + buf * 18432 + rowB * 144 + colB;

            float s[8][4];
            #pragma unroll
            for (int nt = 0; nt < 8; nt++)
                s[nt][0] = s[nt][1] = s[nt][2] = s[nt][3] = 0.f;
            #pragma unroll
            for (int ks = 0; ks < 6; ks++) {
                #pragma unroll
                for (int np = 0; np < 4; np++) {
                    uint32_t bq[4];
                    ldsm4(bq, kBase + np * 3328 + ks * 32);
                    mma16816(s[2 * np],     aQ[ks], bq[0], bq[1]);
                    mma16816(s[2 * np + 1], aQ[ks], bq[2], bq[3]);
                }
            }

            #pragma unroll
            for (int nt = 0; nt < 8; nt++) {
                s[nt][0] = __expf(s[nt][0]);
                s[nt][1] = __expf(s[nt][1]);
                s[nt][2] = __expf(s[nt][2]);
                s[nt][3] = __expf(s[nt][3]);
                rsum0 += s[nt][0] + s[nt][1];
                rsum1 += s[nt][2] + s[nt][3];
            }

            #pragma unroll
            for (int ks = 0; ks < 4; ks++) {
                const int ta = 2 * ks, tb_ = 2 * ks + 1;
                uint32_t ah[4], al[4];
                {
                    float p0 = s[ta][0],  p1 = s[ta][1];
                    float h0 = bf_round(p0), h1 = bf_round(p1);
                    ah[0] = pack2(h1, h0); al[0] = pack2(p1 - h1, p0 - h0);
                    p0 = s[ta][2]; p1 = s[ta][3];
                    h0 = bf_round(p0); h1 = bf_round(p1);
                    ah[1] = pack2(h1, h0); al[1] = pack2(p1 - h1, p0 - h0);
                    p0 = s[tb_][0]; p1 = s[tb_][1];
                    h0 = bf_round(p0); h1 = bf_round(p1);
                    ah[2] = pack2(h1, h0); al[2] = pack2(p1 - h1, p0 - h0);
                    p0 = s[tb_][2]; p1 = s[tb_][3];
                    h0 = bf_round(p0); h1 = bf_round(p1);
                    ah[3] = pack2(h1, h0); al[3] = pack2(p1 - h1, p0 - h0);
                }
                #pragma unroll
                for (int np = 0; np < 4; np++) {
                    uint32_t bhq[4], blq[4];
                    ldsm4(bhq, vBase + np * 2304 + ks * 32);
                    ldsm4(blq, vBase + 9216 + np * 2304 + ks * 32);
                    mma16816(o[2 * np],     ah, bhq[0], bhq[1]);
                    mma16816(o[2 * np],     ah, blq[0], blq[1]);
                    mma16816(o[2 * np],     al, bhq[0], bhq[1]);
                    mma16816(o[2 * np + 1], ah, bhq[2], bhq[3]);
                    mma16816(o[2 * np + 1], ah, blq[2], blq[3]);
                    mma16816(o[2 * np + 1], al, bhq[2], bhq[3]);
                }
            }
            __syncthreads();
            buf ^= 1;
        }

        rsum0 += __shfl_xor_sync(0xffffffffu, rsum0, 1);
        rsum0 += __shfl_xor_sync(0xffffffffu, rsum0, 2);
        rsum1 += __shfl_xor_sync(0xffffffffu, rsum1, 1);
        rsum1 += __shfl_xor_sync(0xffffffffu, rsum1, 2);
        const float inv0 = 1.f / rsum0, inv1 = 1.f / rsum1;

        // ---- phase A: transpose O into sO[d][132 q]; load v halo window ----
        __syncthreads();
        #pragma unroll
        for (int nt = 0; nt < 8; nt++) {
            int d = nt * 8 + 2 * tig;
            int q = wid * 16 + g;
            sO[d * 132 + q]           = o[nt][0] * inv0;
            sO[(d + 1) * 132 + q]     = o[nt][1] * inv0;
            sO[d * 132 + q + 8]       = o[nt][2] * inv1;
            sO[(d + 1) * 132 + q + 8] = o[nt][3] * inv1;
        }
        float* sV = (float*)(sm + ASM_W);
        const int nbase = q0 - 41;
        for (int idx = tid; idx < 210 * 64; idx += 256) {
            int j = idx % 210, d = idx / 210;
            int n = nbase + j;
            float v = 0.f;
            if (n >= 0 && n < NPIX)
                v = __bfloat162float(vhp[(size_t)d * 1600 + n]) +
                    __bfloat162float(vlp[(size_t)d * 1600 + n]);
            sV[d * 211 + j] = v;
        }
        __syncthreads();

        // ---- phase B: y = O + BN(dwconv3x3(v)) ----
        const int b = bh >> 3, h = bh & 7;
        const int dd = tid & 63;
        const int qg = tid >> 6;
        const int cc = h * 64 + dd;
        float w9[9];
        #pragma unroll
        for (int k = 0; k < 9; k++) w9[k] = pw[cc * 9 + k];
        const float pinv = pg[cc] * rsqrtf(pv[cc] + EPSV);
        const float padd = pb[cc] - pm[cc] * pinv;
        const float* vrow = sV + dd * 211;

        float yv[32];
        #pragma unroll 4
        for (int j2 = 0; j2 < 32; j2++) {
            int q = qg * 32 + j2;
            int n = q0 + q;
            int py = n / IW, px = n - py * IW;
            int col = q + 41;
            float s = 0.f;
            #pragma unroll
            for (int dy = -1; dy <= 1; dy++) {
                if (py + dy < 0 || py + dy >= IH) continue;
                int cb = col + dy * IW;
                if (px > 0)      s += w9[(dy + 1) * 3 + 0] * vrow[cb - 1];
                s += w9[(dy + 1) * 3 + 1] * vrow[cb];
                if (px < IW - 1) s += w9[(dy + 1) * 3 + 2] * vrow[cb + 1];
            }
            yv[j2] = s * pinv + padd + sO[dd * 132 + q];
        }
        __syncthreads();

        // ---- phase C: triple-split y into sY[q][208] ----
        __nv_bfloat16* sY = (__nv_bfloat16*)(sm + ASM_W);
        #pragma unroll
        for (int j2 = 0; j2 < 32; j2++) {
            int q = qg * 32 + j2;
            float y = yv[j2];
            float hh = bf_round(y);
            __nv_bfloat16 hb = __float2bfloat16_rn(hh);
            sY[q * 208 + 3 * dd]     = hb;
            sY[q * 208 + 3 * dd + 1] = __float2bfloat16_rn(y - hh);
            sY[q * 208 + 3 * dd + 2] = hb;
        }
        __syncthreads();

        // ---- phase D: vectorized store rows into g_xc ----
        __nv_bfloat16* xd = g_xc + (size_t)b * NPIX * K3 + (size_t)q0 * K3 + h * 192;
        for (int c = tid; c < 128 * 24; c += 256) {
            int row = c / 24, seg = c % 24;
            if (q0 + row < NPIX)
                *(float4*)(xd + (size_t)row * K3 + seg * 8) = *(const float4*)&sY[row * 208 + seg * 8];
        }
    }
}

// ============================================================================
extern "C" void kernel_launch(void* const* d_in, const int* in_sizes, int n_in,
                              void* d_out, int out_size)
{
    const float* x      = (const float*)d_in[0];
    const float* qkv_w  = (const float*)d_in[1];
    const float* qkv_g  = (const float*)d_in[2];
    const float* qkv_b  = (const float*)d_in[3];
    const float* qkv_m  = (const float*)d_in[4];
    const float* qkv_v  = (const float*)d_in[5];
    const float* pe_w   = (const float*)d_in[6];
    const float* pe_g   = (const float*)d_in[7];
    const float* pe_b   = (const float*)d_in[8];
    const float* pe_m   = (const float*)d_in[9];
    const float* pe_v   = (const float*)d_in[10];
    const float* proj_w = (const float*)d_in[11];
    const float* proj_g = (const float*)d_in[12];
    const float* proj_b = (const float*)d_in[13];
    const float* proj_m = (const float*)d_in[14];
    const float* proj_v = (const float*)d_in[15];
    float* out = (float*)d_out;

    __nv_bfloat16 *wcq, *wcp, *xcb;
    cudaGetSymbolAddress((void**)&wcq, g_wcq);
    cudaGetSymbolAddress((void**)&wcp, g_wcp);
    cudaGetSymbolAddress((void**)&xcb, g_xc);

    cudaFuncSetAttribute(gemm3_bn, cudaFuncAttributeMaxDynamicSharedMemorySize, GSMEM);
    cudaFuncSetAttribute(attn2_kernel, cudaFuncAttributeMaxDynamicSharedMemorySize, ASMEM);

    // 0) operand prep (triple-bf16)
    prep_w<<<(HQKV * 512 + 255) / 256, 256>>>(qkv_w, wcq, HQKV * 512);
    prep_w<<<(C * 512 + 255) / 256, 256>>>(proj_w, wcp, C * 512);
    prep_xt<<<dim3(16, 25, B), 256>>>(x, xcb);

    // 1) qkv GEMM (persistent) with fused attention-operand epilogue
    gemm3_bn<<<PGRID, 256, GSMEM>>>(
        wcq, xcb, qkv_g, qkv_b, qkv_m, qkv_v, nullptr, HQKV, 1, 13 * 8 * B);

    // 2) attention (persistent); epilogue does pe conv + add + y -> g_xc
    attn2_kernel<<<PGRID, 256, ASMEM>>>(pe_w, pe_g, pe_b, pe_m, pe_v);

    // 3) out = BN(conv1x1(y, proj_w)) (persistent)
    gemm3_bn<<<PGRID, 256, GSMEM>>>(
        wcp, xcb, proj_g, proj_b, proj_m, proj_v, out, C, 0, 13 * 4 * B);
}

// round 17
// speedup vs baseline: 1.0319x; 1.0319x over previous
#include <cuda_runtime.h>
#include <cuda_bf16.h>
#include <cstdint>
#include <math.h>

#define EPSV 1e-5f
constexpr int B     = 8;
constexpr int C     = 512;
constexpr int NH    = 8;
constexpr int KD    = 32;
constexpr int HD    = 64;
constexpr int HQKV  = 1024;
constexpr int NPIX  = 1600;
constexpr int IH    = 40;
constexpr int IW    = 40;
constexpr int K3    = 1536;
constexpr float SCALE = 0.17677669529663687f;

__device__ __align__(16) __nv_bfloat16 g_wcq[(size_t)HQKV * K3];
__device__ __align__(16) __nv_bfloat16 g_wcp[(size_t)C * K3];
__device__ __align__(16) __nv_bfloat16 g_xc [(size_t)B * NPIX * K3];
__device__ __align__(16) __nv_bfloat16 g_qt[(size_t)64 * 1664 * 96];
__device__ __align__(16) __nv_bfloat16 g_kt[(size_t)64 * 1600 * 96];
__device__ __align__(16) __nv_bfloat16 g_vh[(size_t)64 * 64 * 1600];
__device__ __align__(16) __nv_bfloat16 g_vl[(size_t)64 * 64 * 1600];

// ===================== helpers =====================
__device__ __forceinline__ float bf_round(float x) {
    return __bfloat162float(__float2bfloat16_rn(x));
}
__device__ __forceinline__ uint32_t pack2(float hi, float lo) {
    uint32_t r;
    asm("cvt.rn.bf16x2.f32 %0, %1, %2;" : "=r"(r) : "f"(hi), "f"(lo));
    return r;
}
__device__ __forceinline__ void mma16816(float* c, const uint32_t* a, uint32_t b0, uint32_t b1) {
    asm volatile(
        "mma.sync.aligned.m16n8k16.row.col.f32.bf16.bf16.f32 "
        "{%0,%1,%2,%3}, {%4,%5,%6,%7}, {%8,%9}, {%0,%1,%2,%3};"
        : "+f"(c[0]), "+f"(c[1]), "+f"(c[2]), "+f"(c[3])
        : "r"(a[0]), "r"(a[1]), "r"(a[2]), "r"(a[3]), "r"(b0), "r"(b1));
}
__device__ __forceinline__ void ldsm4(uint32_t* r, uint32_t a) {
    asm volatile("ldmatrix.sync.aligned.m8n8.x4.shared.b16 {%0,%1,%2,%3}, [%4];"
        : "=r"(r[0]), "=r"(r[1]), "=r"(r[2]), "=r"(r[3]) : "r"(a));
}
__device__ __forceinline__ void cp16(uint32_t dst, const void* src) {
    asm volatile("cp.async.cg.shared.global [%0], [%1], 16;" :: "r"(dst), "l"(src));
}
#define CP_COMMIT() asm volatile("cp.async.commit_group;" ::: "memory")
#define CP_WAIT(n)  asm volatile("cp.async.wait_group %0;" :: "n"(n) : "memory")

// ================= prep: W -> triple bf16 [m][3k]: (h,h,l) ==================
__global__ __launch_bounds__(256) void prep_w(const float* __restrict__ W,
                                              __nv_bfloat16* __restrict__ out, int MK)
{
    int i = blockIdx.x * 256 + threadIdx.x;
    if (i >= MK) return;
    int m = i >> 9, k = i & 511;
    float v = W[i];
    float h = bf_round(v);
    __nv_bfloat16* d = out + (size_t)m * K3 + 3 * k;
    d[0] = __float2bfloat16_rn(h);
    d[1] = __float2bfloat16_rn(h);
    d[2] = __float2bfloat16_rn(v - h);
}

// ====== prep: X [b][k][n] -> triple bf16 [b][n][3k]: (h,l,h), vectorized ====
__global__ __launch_bounds__(256) void prep_xt(const float* __restrict__ X,
                                               __nv_bfloat16* __restrict__ out)
{
    __shared__ __align__(16) __nv_bfloat16 s[64 * 112];
    const int tid = threadIdx.x;
    const int k0 = blockIdx.x * 32, n0 = blockIdx.y * 64, b = blockIdx.z;
    const float* Xb = X + (size_t)b * 512 * NPIX;

    #pragma unroll
    for (int i = 0; i < 8; i++) {
        int idx = tid + i * 256;
        int k = idx >> 6, n = idx & 63;
        float v = Xb[(size_t)(k0 + k) * NPIX + n0 + n];
        float h = bf_round(v);
        __nv_bfloat16 hb = __float2bfloat16_rn(h);
        s[n * 112 + 3 * k]     = hb;
        s[n * 112 + 3 * k + 1] = __float2bfloat16_rn(v - h);
        s[n * 112 + 3 * k + 2] = hb;
    }
    __syncthreads();

    __nv_bfloat16* dst = out + (size_t)b * NPIX * K3 + (size_t)n0 * K3 + k0 * 3;
    #pragma unroll
    for (int i = 0; i < 3; i++) {
        int c = tid + i * 256;
        int row = c / 12, col = c % 12;
        float4 val = *(const float4*)&s[row * 112 + col * 8];
        *(float4*)(dst + (size_t)row * K3 + col * 8) = val;
    }
}

// ====== 3-stage single-sync bf16 GEMM (K'=1536, KC=64) + fused BN ===========
constexpr int KC    = 64;
constexpr int NIT   = K3 / KC;                 // 24
constexpr int OPB   = 128 * 144;
constexpr int STAGE = 2 * OPB;                 // 36864
constexpr int GSMEM = 3 * STAGE;               // 110592

__global__ __launch_bounds__(256, 2) void gemm3_bn(
    const __nv_bfloat16* __restrict__ wc, const __nv_bfloat16* __restrict__ xc,
    const float* __restrict__ gamma, const float* __restrict__ beta,
    const float* __restrict__ mean,  const float* __restrict__ var,
    float* __restrict__ out, int M, int fuse)
{
    extern __shared__ __align__(16) char dsm[];
    __shared__ float sbn[128][2];

    const int tid  = threadIdx.x;
    const int wid  = tid >> 5;
    const int lane = tid & 31;
    const int g    = lane >> 2;
    const int tig  = lane & 3;
    const int wm   = wid >> 1;
    const int wn   = wid & 1;
    const int n0   = blockIdx.x * 128;
    const int m0   = blockIdx.y * 128;
    const int b    = blockIdx.z;
    const __nv_bfloat16* xb = xc + (size_t)b * NPIX * K3;

    if (tid < 128) {
        int m = m0 + tid;
        float inv = gamma[m] * rsqrtf(var[m] + EPSV);
        sbn[tid][0] = inv;
        sbn[tid][1] = beta[m] - mean[m] * inv;
    }

    const uint32_t sb = (uint32_t)__cvta_generic_to_shared(dsm);

    const int rowA = wm * 32 + (lane & 15);
    const uint32_t colA = (lane & 16) ? 16u : 0u;
    const int rowB = (lane & 7) + ((lane & 16) >> 1);
    const uint32_t colB = (lane & 8) ? 16u : 0u;

    int rowL[4], segL[4], nCl[4];
    #pragma unroll
    for (int j = 0; j < 4; j++) {
        int id = tid + j * 256;
        rowL[j] = id >> 3; segL[j] = id & 7;
        int n = n0 + rowL[j]; if (n > NPIX - 1) n = NPIX - 1;
        nCl[j] = n;
    }

    float acc[2][8][4];
    #pragma unroll
    for (int i = 0; i < 2; i++)
        #pragma unroll
        for (int j = 0; j < 8; j++)
            #pragma unroll
            for (int l = 0; l < 4; l++) acc[i][j][l] = 0.f;

    auto issue = [&](int buf, int k0) {
        uint32_t bo = sb + buf * STAGE;
        #pragma unroll
        for (int j = 0; j < 4; j++) {
            uint32_t d = rowL[j] * 144 + segL[j] * 16;
            cp16(bo + d,       wc + (size_t)(m0 + rowL[j]) * K3 + k0 + segL[j] * 8);
            cp16(bo + OPB + d, xb + (size_t)nCl[j] * K3 + k0 + segL[j] * 8);
        }
    };

    issue(0, 0);  CP_COMMIT();
    issue(1, KC); CP_COMMIT();

    int rd = 0, wr = 2;
    #pragma unroll 1
    for (int it = 0; it < NIT; it++) {
        CP_WAIT(1);
        __syncthreads();
        if (it + 2 < NIT) issue(wr, (it + 2) * KC);
        CP_COMMIT();

        const uint32_t aBase = sb + rd * STAGE + rowA * 144 + colA;
        const uint32_t bBase = sb + rd * STAGE + OPB + (wn * 64 + rowB) * 144 + colB;
        #pragma unroll
        for (int ks = 0; ks < 4; ks++) {
            uint32_t aW[2][4];
            ldsm4(aW[0], aBase + ks * 32);
            ldsm4(aW[1], aBase + 2304 + ks * 32);
            #pragma unroll
            for (int np = 0; np < 4; np++) {
                uint32_t bq[4];
                ldsm4(bq, bBase + np * 2304 + ks * 32);
                mma16816(acc[0][2 * np],     aW[0], bq[0], bq[1]);
                mma16816(acc[1][2 * np],     aW[1], bq[0], bq[1]);
                mma16816(acc[0][2 * np + 1], aW[0], bq[2], bq[3]);
                mma16816(acc[1][2 * np + 1], aW[1], bq[2], bq[3]);
            }
        }
        rd = (rd == 2) ? 0 : rd + 1;
        wr = (wr == 2) ? 0 : wr + 1;
    }

    if (!fuse) {
        #pragma unroll
        for (int mf = 0; mf < 2; mf++) {
            int mla = wm * 32 + mf * 16 + g;
            int mlb = mla + 8;
            float inva = sbn[mla][0], adda = sbn[mla][1];
            float invb = sbn[mlb][0], addb = sbn[mlb][1];
            float* rowa = out + ((size_t)b * M + m0 + mla) * NPIX;
            float* rowb = out + ((size_t)b * M + m0 + mlb) * NPIX;
            #pragma unroll
            for (int nf = 0; nf < 8; nf++) {
                int n = n0 + wn * 64 + nf * 8 + 2 * tig;
                if (n < NPIX) {
                    *(float2*)&rowa[n] = make_float2(acc[mf][nf][0] * inva + adda,
                                                     acc[mf][nf][1] * inva + adda);
                    *(float2*)&rowb[n] = make_float2(acc[mf][nf][2] * invb + addb,
                                                     acc[mf][nf][3] * invb + addb);
                }
            }
        }
        return;
    }

    // ---- fused qkv epilogue ----
    const int bh = b * NH + (m0 >> 7);
    __syncthreads();
    __nv_bfloat16* sq  = (__nv_bfloat16*)dsm;            // [128 n][104]
    __nv_bfloat16* sk2 = (__nv_bfloat16*)(dsm + 26624);  // [128 n][104]

    if (wm < 2) {
        __nv_bfloat16* sdst = (wm == 0) ? sq : sk2;
        const bool isQ = (wm == 0);
        #pragma unroll
        for (int mf = 0; mf < 2; mf++) {
            #pragma unroll
            for (int e = 0; e < 2; e++) {
                int c  = mf * 16 + g + e * 8;
                int ml = wm * 32 + c;
                float inv = sbn[ml][0], add = sbn[ml][1];
                #pragma unroll
                for (int nf = 0; nf < 8; nf++) {
                    int nl = wn * 64 + nf * 8 + 2 * tig;
                    float v0 = acc[mf][nf][2 * e]     * inv + add;
                    float v1 = acc[mf][nf][2 * e + 1] * inv + add;
                    if (isQ) { v0 *= SCALE; v1 *= SCALE; }
                    float h0 = bf_round(v0), h1 = bf_round(v1);
                    __nv_bfloat16 hb0 = __float2bfloat16_rn(h0);
                    __nv_bfloat16 hb1 = __float2bfloat16_rn(h1);
                    __nv_bfloat16 lb0 = __float2bfloat16_rn(v0 - h0);
                    __nv_bfloat16 lb1 = __float2bfloat16_rn(v1 - h1);
                    if (isQ) {
                        sdst[nl * 104 + 3 * c]     = hb0;
                        sdst[nl * 104 + 3 * c + 1] = hb0;
                        sdst[nl * 104 + 3 * c + 2] = lb0;
                        sdst[(nl + 1) * 104 + 3 * c]     = hb1;
                        sdst[(nl + 1) * 104 + 3 * c + 1] = hb1;
                        sdst[(nl + 1) * 104 + 3 * c + 2] = lb1;
                    } else {
                        sdst[nl * 104 + 3 * c]     = hb0;
                        sdst[nl * 104 + 3 * c + 1] = lb0;
                        sdst[nl * 104 + 3 * c + 2] = hb0;
                        sdst[(nl + 1) * 104 + 3 * c]     = hb1;
                        sdst[(nl + 1) * 104 + 3 * c + 1] = lb1;
                        sdst[(nl + 1) * 104 + 3 * c + 2] = hb1;
                    }
                }
            }
        }
    } else {
        #pragma unroll
        for (int mf = 0; mf < 2; mf++) {
            #pragma unroll
            for (int e = 0; e < 2; e++) {
                int ml = wm * 32 + mf * 16 + g + e * 8;
                int d  = ml - 64;
                float inv = sbn[ml][0], add = sbn[ml][1];
                __nv_bfloat16* vhrow = g_vh + ((size_t)bh * 64 + d) * 1600;
                __nv_bfloat16* vlrow = g_vl + ((size_t)bh * 64 + d) * 1600;
                #pragma unroll
                for (int nf = 0; nf < 8; nf++) {
                    int n = n0 + wn * 64 + nf * 8 + 2 * tig;
                    if (n < NPIX) {
                        float v0 = acc[mf][nf][2 * e]     * inv + add;
                        float v1 = acc[mf][nf][2 * e + 1] * inv + add;
                        float h0 = bf_round(v0), h1 = bf_round(v1);
                        *(uint32_t*)(vhrow + n) = pack2(h1, h0);
                        *(uint32_t*)(vlrow + n) = pack2(v1 - h1, v0 - h0);
                    }
                }
            }
        }
    }
    __syncthreads();

    __nv_bfloat16* qd = g_qt + ((size_t)bh * 1664 + n0) * 96;
    __nv_bfloat16* kd = g_kt + ((size_t)bh * 1600 + n0) * 96;
    #pragma unroll
    for (int i = 0; i < 6; i++) {
        int cch = tid + i * 256;
        int row = cch / 12, seg = cch % 12;
        *(float4*)(qd + (size_t)row * 96 + seg * 8) = *(const float4*)&sq[row * 104 + seg * 8];
        if (n0 + row < NPIX)
            *(float4*)(kd + (size_t)row * 96 + seg * 8) = *(const float4*)&sk2[row * 104 + seg * 8];
    }
}

// ===== attention: 3-stage single-sync ring + fused pe/y epilogue ===========
// smem: stage C @ 0 (sQ aliases 0..26624), stage A @ 31744, stage B @ 63488.
// Each stage: K 64x208B (13312) then Vh/Vl 64x144B (9216+9216) = 31744.
// Epilogue: sO (64x132 f32 @0), sV/sY @ 33792.
constexpr int ASTG  = 31744;
constexpr int ASM_W = 33792;
constexpr int ASMEM = 95232;

__global__ __launch_bounds__(256, 2) void attn2_kernel(
    const float* __restrict__ pw,
    const float* __restrict__ pg, const float* __restrict__ pb,
    const float* __restrict__ pm, const float* __restrict__ pv)
{
    extern __shared__ __align__(16) char sm[];
    const uint32_t sb = (uint32_t)__cvta_generic_to_shared(sm);
    const __nv_bfloat16* sQ = (const __nv_bfloat16*)sm;
    float* sO = (float*)sm;

    const int tid  = threadIdx.x;
    const int wid  = tid >> 5;
    const int lane = tid & 31;
    const int g    = lane >> 2;
    const int tig  = lane & 3;
    const int bh   = blockIdx.y;
    const int q0   = blockIdx.x * 128;

    const int rowB = (lane & 7) + ((lane & 16) >> 1);
    const uint32_t colB = (lane & 8) ? 16u : 0u;

    const __nv_bfloat16* qt  = g_qt + (size_t)bh * 1664 * 96;
    const __nv_bfloat16* kt  = g_kt + (size_t)bh * 1600 * 96;
    const __nv_bfloat16* vhp = g_vh + (size_t)bh * 64 * 1600;
    const __nv_bfloat16* vlp = g_vl + (size_t)bh * 64 * 1600;

    // stage offset for KV tile t: t%3 -> {A, B, C}
    auto stOff = [](int t) -> uint32_t {
        int m = t % 3;
        return (m == 0) ? 31744u : (m == 1) ? 63488u : 0u;
    };

    auto issueKV = [&](uint32_t so, int t) {
        uint32_t kb = sb + so;
        #pragma unroll
        for (int j = 0; j < 3; j++) {
            int id = tid + j * 256;
            int row = id / 12, seg = id % 12;
            cp16(kb + row * 208 + seg * 16, kt + ((size_t)(t * 64 + row)) * 96 + seg * 8);
        }
        uint32_t vb = kb + 13312;
        #pragma unroll
        for (int j = 0; j < 4; j++) {
            int id = tid + j * 256;
            int half = id >> 9, r = id & 511;
            int row = r >> 3, seg = r & 7;
            const __nv_bfloat16* src = (half ? vlp : vhp) + (size_t)row * 1600 + t * 64 + seg * 8;
            cp16(vb + half * 9216 + row * 144 + seg * 16, src);
        }
    };

    // prologue: G0 = Q (into C region) + KV0 (into A); G1 = KV1 (into B)
    #pragma unroll
    for (int j = 0; j < 6; j++) {
        int id = tid + j * 256;
        int row = id / 12, seg = id % 12;
        cp16(sb + row * 208 + seg * 16, qt + (size_t)(q0 + row) * 96 + seg * 8);
    }
    issueKV(31744u, 0);
    CP_COMMIT();
    issueKV(63488u, 1);
    CP_COMMIT();

    uint32_t aQ[6][4];
    float o[8][4];
    #pragma unroll
    for (int i = 0; i < 8; i++)
        #pragma unroll
        for (int j = 0; j < 4; j++) o[i][j] = 0.f;
    float rsum0 = 0.f, rsum1 = 0.f;

    #pragma unroll 1
    for (int t = 0; t < 25; t++) {
        CP_WAIT(1);
        __syncthreads();

        if (t == 0) {
            // read Q fragments from sQ (C region), then barrier before any
            // thread issues stage-C writes (KV2 aliases sQ)
            int r0 = wid * 16 + g;
            #pragma unroll
            for (int ks = 0; ks < 6; ks++) {
                int cb = ks * 16 + 2 * tig;
                aQ[ks][0] = *(const uint32_t*)&sQ[r0 * 104 + cb];
                aQ[ks][1] = *(const uint32_t*)&sQ[(r0 + 8) * 104 + cb];
                aQ[ks][2] = *(const uint32_t*)&sQ[r0 * 104 + cb + 8];
                aQ[ks][3] = *(const uint32_t*)&sQ[(r0 + 8) * 104 + cb + 8];
            }
            __syncthreads();
        }

        if (t + 2 < 25) issueKV(stOff(t + 2), t + 2);
        CP_COMMIT();

        const uint32_t so = stOff(t);
        const uint32_t kBase = sb + so + rowB * 208 + colB;
        const uint32_t vBase = sb + so + 13312 + rowB * 144 + colB;

        float s[8][4];
        #pragma unroll
        for (int nt = 0; nt < 8; nt++)
            s[nt][0] = s[nt][1] = s[nt][2] = s[nt][3] = 0.f;
        #pragma unroll
        for (int ks = 0; ks < 6; ks++) {
            #pragma unroll
            for (int np = 0; np < 4; np++) {
                uint32_t bq[4];
                ldsm4(bq, kBase + np * 3328 + ks * 32);
                mma16816(s[2 * np],     aQ[ks], bq[0], bq[1]);
                mma16816(s[2 * np + 1], aQ[ks], bq[2], bq[3]);
            }
        }

        #pragma unroll
        for (int nt = 0; nt < 8; nt++) {
            s[nt][0] = __expf(s[nt][0]);
            s[nt][1] = __expf(s[nt][1]);
            s[nt][2] = __expf(s[nt][2]);
            s[nt][3] = __expf(s[nt][3]);
            rsum0 += s[nt][0] + s[nt][1];
            rsum1 += s[nt][2] + s[nt][3];
        }

        #pragma unroll
        for (int ks = 0; ks < 4; ks++) {
            const int ta = 2 * ks, tb_ = 2 * ks + 1;
            uint32_t ah[4], al[4];
            {
                float p0 = s[ta][0],  p1 = s[ta][1];
                float h0 = bf_round(p0), h1 = bf_round(p1);
                ah[0] = pack2(h1, h0); al[0] = pack2(p1 - h1, p0 - h0);
                p0 = s[ta][2]; p1 = s[ta][3];
                h0 = bf_round(p0); h1 = bf_round(p1);
                ah[1] = pack2(h1, h0); al[1] = pack2(p1 - h1, p0 - h0);
                p0 = s[tb_][0]; p1 = s[tb_][1];
                h0 = bf_round(p0); h1 = bf_round(p1);
                ah[2] = pack2(h1, h0); al[2] = pack2(p1 - h1, p0 - h0);
                p0 = s[tb_][2]; p1 = s[tb_][3];
                h0 = bf_round(p0); h1 = bf_round(p1);
                ah[3] = pack2(h1, h0); al[3] = pack2(p1 - h1, p0 - h0);
            }
            #pragma unroll
            for (int np = 0; np < 4; np++) {
                uint32_t bhq[4], blq[4];
                ldsm4(bhq, vBase + np * 2304 + ks * 32);
                ldsm4(blq, vBase + 9216 + np * 2304 + ks * 32);
                mma16816(o[2 * np],     ah, bhq[0], bhq[1]);
                mma16816(o[2 * np],     ah, blq[0], blq[1]);
                mma16816(o[2 * np],     al, bhq[0], bhq[1]);
                mma16816(o[2 * np + 1], ah, bhq[2], bhq[3]);
                mma16816(o[2 * np + 1], ah, blq[2], blq[3]);
                mma16816(o[2 * np + 1], al, bhq[2], bhq[3]);
            }
        }
    }

    rsum0 += __shfl_xor_sync(0xffffffffu, rsum0, 1);
    rsum0 += __shfl_xor_sync(0xffffffffu, rsum0, 2);
    rsum1 += __shfl_xor_sync(0xffffffffu, rsum1, 1);
    rsum1 += __shfl_xor_sync(0xffffffffu, rsum1, 2);
    const float inv0 = 1.f / rsum0, inv1 = 1.f / rsum1;

    // ---- phase A: transpose O into sO[d][132 q]; load v halo window ----
    __syncthreads();
    #pragma unroll
    for (int nt = 0; nt < 8; nt++) {
        int d = nt * 8 + 2 * tig;
        int q = wid * 16 + g;
        sO[d * 132 + q]           = o[nt][0] * inv0;
        sO[(d + 1) * 132 + q]     = o[nt][1] * inv0;
        sO[d * 132 + q + 8]       = o[nt][2] * inv1;
        sO[(d + 1) * 132 + q + 8] = o[nt][3] * inv1;
    }
    float* sV = (float*)(sm + ASM_W);
    const int nbase = q0 - 41;
    for (int idx = tid; idx < 210 * 64; idx += 256) {
        int j = idx % 210, d = idx / 210;
        int n = nbase + j;
        float v = 0.f;
        if (n >= 0 && n < NPIX)
            v = __bfloat162float(vhp[(size_t)d * 1600 + n]) +
                __bfloat162float(vlp[(size_t)d * 1600 + n]);
        sV[d * 211 + j] = v;
    }
    __syncthreads();

    // ---- phase B: y = O + BN(dwconv3x3(v)) ----
    const int b = bh >> 3, h = bh & 7;
    const int dd = tid & 63;
    const int qg = tid >> 6;
    const int cc = h * 64 + dd;
    float w9[9];
    #pragma unroll
    for (int k = 0; k < 9; k++) w9[k] = pw[cc * 9 + k];
    const float pinv = pg[cc] * rsqrtf(pv[cc] + EPSV);
    const float padd = pb[cc] - pm[cc] * pinv;
    const float* vrow = sV + dd * 211;

    float yv[32];
    #pragma unroll 4
    for (int j2 = 0; j2 < 32; j2++) {
        int q = qg * 32 + j2;
        int n = q0 + q;
        int py = n / IW, px = n - py * IW;
        int col = q + 41;
        float s = 0.f;
        #pragma unroll
        for (int dy = -1; dy <= 1; dy++) {
            if (py + dy < 0 || py + dy >= IH) continue;
            int cb = col + dy * IW;
            if (px > 0)      s += w9[(dy + 1) * 3 + 0] * vrow[cb - 1];
            s += w9[(dy + 1) * 3 + 1] * vrow[cb];
            if (px < IW - 1) s += w9[(dy + 1) * 3 + 2] * vrow[cb + 1];
        }
        yv[j2] = s * pinv + padd + sO[dd * 132 + q];
    }
    __syncthreads();

    // ---- phase C: triple-split y into sY[q][208] ----
    __nv_bfloat16* sY = (__nv_bfloat16*)(sm + ASM_W);
    #pragma unroll
    for (int j2 = 0; j2 < 32; j2++) {
        int q = qg * 32 + j2;
        float y = yv[j2];
        float hh = bf_round(y);
        __nv_bfloat16 hb = __float2bfloat16_rn(hh);
        sY[q * 208 + 3 * dd]     = hb;
        sY[q * 208 + 3 * dd + 1] = __float2bfloat16_rn(y - hh);
        sY[q * 208 + 3 * dd + 2] = hb;
    }
    __syncthreads();

    // ---- phase D: vectorized store rows into g_xc (proj operand layout) ----
    __nv_bfloat16* xd = g_xc + (size_t)b * NPIX * K3 + (size_t)q0 * K3 + h * 192;
    for (int c = tid; c < 128 * 24; c += 256) {
        int row = c / 24, seg = c % 24;
        if (q0 + row < NPIX)
            *(float4*)(xd + (size_t)row * K3 + seg * 8) = *(const float4*)&sY[row * 208 + seg * 8];
    }
}

// ============================================================================
extern "C" void kernel_launch(void* const* d_in, const int* in_sizes, int n_in,
                              void* d_out, int out_size)
{
    const float* x      = (const float*)d_in[0];
    const float* qkv_w  = (const float*)d_in[1];
    const float* qkv_g  = (const float*)d_in[2];
    const float* qkv_b  = (const float*)d_in[3];
    const float* qkv_m  = (const float*)d_in[4];
    const float* qkv_v  = (const float*)d_in[5];
    const float* pe_w   = (const float*)d_in[6];
    const float* pe_g   = (const float*)d_in[7];
    const float* pe_b   = (const float*)d_in[8];
    const float* pe_m   = (const float*)d_in[9];
    const float* pe_v   = (const float*)d_in[10];
    const float* proj_w = (const float*)d_in[11];
    const float* proj_g = (const float*)d_in[12];
    const float* proj_b = (const float*)d_in[13];
    const float* proj_m = (const float*)d_in[14];
    const float* proj_v = (const float*)d_in[15];
    float* out = (float*)d_out;

    __nv_bfloat16 *wcq, *wcp, *xcb;
    cudaGetSymbolAddress((void**)&wcq, g_wcq);
    cudaGetSymbolAddress((void**)&wcp, g_wcp);
    cudaGetSymbolAddress((void**)&xcb, g_xc);

    cudaFuncSetAttribute(gemm3_bn, cudaFuncAttributeMaxDynamicSharedMemorySize, GSMEM);
    cudaFuncSetAttribute(attn2_kernel, cudaFuncAttributeMaxDynamicSharedMemorySize, ASMEM);

    // 0) operand prep (triple-bf16)
    prep_w<<<(HQKV * 512 + 255) / 256, 256>>>(qkv_w, wcq, HQKV * 512);
    prep_w<<<(C * 512 + 255) / 256, 256>>>(proj_w, wcp, C * 512);
    prep_xt<<<dim3(16, 25, B), 256>>>(x, xcb);

    // 1) qkv GEMM with fused attention-operand epilogue
    gemm3_bn<<<dim3(13, HQKV / 128, B), 256, GSMEM>>>(
        wcq, xcb, qkv_g, qkv_b, qkv_m, qkv_v, nullptr, HQKV, 1);

    // 2) attention (3-stage ring); epilogue does pe conv + add + y -> g_xc
    attn2_kernel<<<dim3(13, 64), 256, ASMEM>>>(pe_w, pe_g, pe_b, pe_m, pe_v);

    // 3) out = BN(conv1x1(y, proj_w))
    gemm3_bn<<<dim3(13, C / 128, B), 256, GSMEM>>>(
        wcp, xcb, proj_g, proj_b, proj_m, proj_v, out, C, 0);
}